// round 12
// baseline (speedup 1.0000x reference)
#include <cuda_runtime.h>
#include <cuda_fp16.h>
#include <math.h>

#define NFEAT 18
#define NTRK  1500
#define BSZ   64
#define NTRACK (BSZ*NTRK)        // 96000
#define HID   256
#define TSTEPS 6
#define NT_TILE 32               // tracks per CTA
#define CTA_THREADS 256

// output layout offsets (floats)
#define OUT_POS   24576000       // 96000*256
#define OUT_LOGPT 36864000       // + 96000*128
#define OUT_ETA   36960000
#define OUT_PHI   37056000

// dynamic smem layout (bytes)
#define H0_OFF    0              // 8192 halves (double-buffered h0)
#define H1_OFF    16384          // 8192 halves
#define SB0_OFF   32768          // 512 f32
#define SB1_OFF   34816          // 512 f32
#define WIH0_OFF  36864          // 1024 f32
#define XIN_OFF   40960          // 12*32 f32
#define F3S_OFF   42496          // 3*32 f32
#define STAGE_OFF 43008          // 8 warps * 8192 B (2 bufs x 4KB)
#define SMEM_BYTES (43008 + 8*8192)

typedef unsigned long long u64;
typedef unsigned int u32;

// ---------------- device scratch: fragment-packed fp16 weights ----------------
// LSTM mats: ((((wi*4 + g)*8 + kc)*32 + lane)*4 + reg)*2 + dd
__device__ __align__(16) __half P_hh0[65536];
__device__ __align__(16) __half P_ih1[65536];
__device__ __align__(16) __half P_hh1[65536];
__device__ __align__(16) __half P_w0 [32768];   // [8w][2mt][8kc][32][4][2]
__device__ __align__(16) __half P_w1 [65536];   // [8w][2kh][2mt][8kc][32][4][2]
__device__ __align__(16) float g_b0c[512];      // b_ih0+b_hh0, row = g*128+unit
__device__ __align__(16) float g_b1c[512];
__device__ float g_posmul[64];

// ---------------- prep: pack weights into mma fragment order ----------------
__global__ void prep_kernel(const float* __restrict__ W_hh0,
                            const float* __restrict__ b_ih0, const float* __restrict__ b_hh0,
                            const float* __restrict__ W_ih1, const float* __restrict__ W_hh1,
                            const float* __restrict__ b_ih1, const float* __restrict__ b_hh1,
                            const float* __restrict__ mw0,   const float* __restrict__ mw1)
{
    int stride = gridDim.x * blockDim.x;
    int idx0 = blockIdx.x * blockDim.x + threadIdx.x;

    for (int i = idx0; i < 65536; i += stride) {
        int dd = i & 1, reg = (i >> 1) & 3, lane = (i >> 3) & 31;
        int kc = (i >> 8) & 7, g = (i >> 11) & 3, w = (i >> 13) & 7;
        int row = g * 128 + w * 16 + (lane >> 2) + 8 * (reg & 1);
        int col = kc * 16 + (lane & 3) * 2 + dd + 8 * (reg >> 1);
        P_hh0[i] = __float2half_rn(W_hh0[row * 128 + col]);
        P_ih1[i] = __float2half_rn(W_ih1[row * 128 + col]);
        P_hh1[i] = __float2half_rn(W_hh1[row * 128 + col]);
    }
    for (int i = idx0; i < 32768; i += stride) {
        int dd = i & 1, reg = (i >> 1) & 3, lane = (i >> 3) & 31;
        int kc = (i >> 8) & 7, mt = (i >> 11) & 1, w = (i >> 12) & 7;
        int row = w * 32 + mt * 16 + (lane >> 2) + 8 * (reg & 1);
        int k   = kc * 16 + (lane & 3) * 2 + dd + 8 * (reg >> 1);
        P_w0[i] = __float2half_rn(mw0[row * 131 + 3 + k]);
    }
    // MLP1, K=256, kh-major: [8w][2kh][2mt][8kc]
    for (int i = idx0; i < 65536; i += stride) {
        int dd = i & 1, reg = (i >> 1) & 3, lane = (i >> 3) & 31;
        int kc = (i >> 8) & 7, mt = (i >> 11) & 1, kh = (i >> 12) & 1, w = (i >> 13) & 7;
        int row = w * 32 + mt * 16 + (lane >> 2) + 8 * (reg & 1);
        int k   = (kh * 8 + kc) * 16 + (lane & 3) * 2 + dd + 8 * (reg >> 1);
        P_w1[i] = __float2half_rn(mw1[row * 256 + k]);
    }
    for (int i = idx0; i < 512; i += stride) {
        g_b0c[i] = b_ih0[i] + b_hh0[i];
        g_b1c[i] = b_ih1[i] + b_hh1[i];
    }
    for (int i = idx0; i < 64; i += stride) {
        float e = (float)(2 * (i >> 1)) * (1.0f / 64.0f);
        g_posmul[i] = 6.283185307179586f / powf(10000.0f, e);
    }
}

// ---------------- activations (MUFU.TANH based) ----------------
__device__ __forceinline__ float tanh_mufu(float x) {
    float r; asm("tanh.approx.f32 %0, %1;" : "=f"(r) : "f"(x)); return r;
}
__device__ __forceinline__ float sigf(float x) {
    return fmaf(tanh_mufu(0.5f * x), 0.5f, 0.5f);
}

// ---------------- cp.async helpers ----------------
__device__ __forceinline__ void cp16(u32 dst_smem, const void* src) {
    asm volatile("cp.async.ca.shared.global [%0], [%1], 16;"
                 :: "r"(dst_smem), "l"(src));
}
__device__ __forceinline__ void cp_commit() {
    asm volatile("cp.async.commit_group;");
}
template<int N>
__device__ __forceinline__ void cp_wait() {
    asm volatile("cp.async.wait_group %0;" :: "n"(N));
}
__device__ __forceinline__ uint4 lds128(u32 addr) {
    uint4 v;
    asm volatile("ld.shared.v4.u32 {%0,%1,%2,%3}, [%4];"
                 : "=r"(v.x), "=r"(v.y), "=r"(v.z), "=r"(v.w) : "r"(addr));
    return v;
}

// ---------------- mma.sync wrapper ----------------
__device__ __forceinline__ void mma16816(float c[4], u32 a0, u32 a1, u32 a2, u32 a3,
                                         u32 b0, u32 b1) {
    asm("mma.sync.aligned.m16n8k16.row.col.f32.f16.f16.f32 "
        "{%0,%1,%2,%3}, {%4,%5,%6,%7}, {%8,%9}, {%0,%1,%2,%3};"
        : "+f"(c[0]), "+f"(c[1]), "+f"(c[2]), "+f"(c[3])
        : "r"(a0), "r"(a1), "r"(a2), "r"(a3), "r"(b0), "r"(b1));
}

// hB layout (half index): unit u = kc*16 + 2c + dd + 8kp
__device__ __forceinline__ int hb_widx(int u, int n) {
    return ((u >> 4) * 4 + ((u & 7) >> 1)) * 128 + n * 4 + ((u >> 3) & 1) * 2 + (u & 1);
}

// ---------------- staged fragment GEMM ----------------
// Stage prologue: lane-private cp.async of chunks 0,1 (2 kc each) into bufs 0,1.
template<int MT, int NKC>
__device__ __forceinline__ void stage_pro(const __half* __restrict__ pw,
                                          u32 sstage, int lane)
{
#pragma unroll
    for (int ch = 0; ch < 2; ++ch) {
#pragma unroll
        for (int kcL = 0; kcL < 2; ++kcL) {
#pragma unroll
            for (int mt = 0; mt < MT; ++mt) {
                int kc = ch * 2 + kcL;
                cp16(sstage + ch * 4096 + ((kcL * MT + mt) * 32 + lane) * 16,
                     (const void*)(pw + ((mt * NKC + kc) * 32 + lane) * 8));
            }
        }
        cp_commit();
    }
}

// Body: consume chunks from stage (LDS), refill 2 chunks ahead.
template<int MT, int NKC>
__device__ __forceinline__ void gemm_body(float acc[][4][4],
                                          const __half* __restrict__ pw,
                                          const __half* __restrict__ hB,
                                          u32 sstage, int lane)
{
    const int c = lane & 3, colr = lane >> 2;
    constexpr int NCH = NKC / 2;
#pragma unroll
    for (int ch = 0; ch < NCH; ++ch) {
        if (ch + 1 < NCH) cp_wait<1>(); else cp_wait<0>();
#pragma unroll
        for (int kcL = 0; kcL < 2; ++kcL) {
            const int kc = ch * 2 + kcL;
            u64 bv[4];
#pragma unroll
            for (int nt = 0; nt < 4; ++nt)
                bv[nt] = *reinterpret_cast<const u64*>(hB + ((kc * 4 + c) * 32 + nt * 8 + colr) * 4);
#pragma unroll
            for (int mt = 0; mt < MT; ++mt) {
                uint4 a = lds128(sstage + (ch & 1) * 4096 + ((kcL * MT + mt) * 32 + lane) * 16);
#pragma unroll
                for (int nt = 0; nt < 4; ++nt)
                    mma16816(acc[mt][nt], a.x, a.y, a.z, a.w,
                             (u32)bv[nt], (u32)(bv[nt] >> 32));
            }
        }
        if (ch + 2 < NCH) {
#pragma unroll
            for (int kcL = 0; kcL < 2; ++kcL) {
#pragma unroll
                for (int mt = 0; mt < MT; ++mt) {
                    int kc = (ch + 2) * 2 + kcL;
                    cp16(sstage + (ch & 1) * 4096 + ((kcL * MT + mt) * 32 + lane) * 16,
                         (const void*)(pw + ((mt * NKC + kc) * 32 + lane) * 8));
                }
            }
            cp_commit();
        }
    }
}

// ---------------- LSTM epilogue (16 units x 32 tracks per warp) ----------------
__device__ __forceinline__ void epi_lstm(float acc[4][4][4], float* cst, __half* hbuf,
                                         int w16, int lr, int c2)
{
#pragma unroll
    for (int nt = 0; nt < 4; ++nt)
#pragma unroll
        for (int idx = 0; idx < 4; ++idx) {
            float iv = sigf(acc[0][nt][idx]);
            float fv = sigf(acc[1][nt][idx]);
            float gv = tanh_mufu(acc[2][nt][idx]);
            float ov = sigf(acc[3][nt][idx]);
            float& cc = cst[nt * 4 + idx];
            cc = fv * cc + iv * gv;
            float h = ov * tanh_mufu(cc);
            int u = w16 + lr + 8 * (idx >> 1);
            int n = nt * 8 + c2 + (idx & 1);
            hbuf[hb_widx(u, n)] = __float2half_rn(h);
        }
}

// ---------------- fused LSTM + MLP (tensor-core, cp.async-staged weights) ----------------
__global__ void __launch_bounds__(CTA_THREADS, 2)
lstm_mlp_kernel(const float* __restrict__ tf,
                const float* __restrict__ W_ih0,   // [512][2] row-major
                const float* __restrict__ mw0,     // [256][131]
                const float* __restrict__ mb0,
                const float* __restrict__ mb1,
                float* __restrict__ out)
{
    extern __shared__ __align__(16) char smem[];
    __half* sh_h0 = (__half*)(smem + H0_OFF);      // [2][4096]
    __half* sh_h1 = (__half*)(smem + H1_OFF);      // [2][4096]
    float* sb0   = (float*)(smem + SB0_OFF);
    float* sb1   = (float*)(smem + SB1_OFF);
    float* swih0 = (float*)(smem + WIH0_OFF);
    float* xin   = (float*)(smem + XIN_OFF);       // [12][32]
    float* f3s   = (float*)(smem + F3S_OFF);       // [3][32]

    u32 smem_u32;
    { u32 a; asm("{ .reg .u64 t; cvta.to.shared.u64 t, %1; cvt.u32.u64 %0, t; }"
                 : "=r"(a) : "l"(smem)); smem_u32 = a; }

    const int tid  = threadIdx.x;
    const int lane = tid & 31;
    const int w    = tid >> 5;
    const int track0 = blockIdx.x * NT_TILE;
    const int lr = lane >> 2, c2 = (lane & 3) * 2;
    const int w16 = w * 16;
    const u32 sstage = smem_u32 + STAGE_OFF + w * 8192;

    for (int i = tid; i < 512; i += CTA_THREADS) { sb0[i] = g_b0c[i]; sb1[i] = g_b1c[i]; }
    for (int i = tid; i < 1024; i += CTA_THREADS) swih0[i] = W_ih0[i];
    for (int i = tid; i < 12 * NT_TILE; i += CTA_THREADS) {
        int f = i >> 5, n = i & 31;
        int gt = track0 + n, b = gt / NTRK, t = gt - b * NTRK;
        xin[f * 32 + n] = tf[((size_t)b * NFEAT + 6 + f) * NTRK + t];
    }
    for (int i = tid; i < 3 * NT_TILE; i += CTA_THREADS) {
        int f = i >> 5, n = i & 31;
        int gt = track0 + n, b = gt / NTRK, t = gt - b * NTRK;
        f3s[f * 32 + n] = tf[((size_t)b * NFEAT + f) * NTRK + t];
    }
    __syncthreads();

    float cst0[16], cst1[16];
#pragma unroll
    for (int i = 0; i < 16; ++i) { cst0[i] = 0.f; cst1[i] = 0.f; }

#pragma unroll 1
    for (int t = 0; t < TSTEPS; ++t) {
        const int cur = t & 1, prv = cur ^ 1;
        float acc[4][4][4];

        // ---------- layer 0: bias + W_ih0 * x_t (+ W_hh0 * h0_prev) ----------
        if (t > 0) stage_pro<4, 8>(P_hh0 + w * 8192, sstage, lane);
#pragma unroll
        for (int g = 0; g < 4; ++g)
#pragma unroll
            for (int uu = 0; uu < 2; ++uu) {
                int row = g * 128 + w16 + lr + 8 * uu;
                float bv = sb0[row];
                float w0v = swih0[row * 2 + 0];
                float w1v = swih0[row * 2 + 1];
#pragma unroll
                for (int nt = 0; nt < 4; ++nt)
#pragma unroll
                    for (int dd = 0; dd < 2; ++dd) {
                        int n = nt * 8 + c2 + dd;
                        acc[g][nt][uu * 2 + dd] =
                            fmaf(w1v, xin[(2 * t + 1) * 32 + n],
                                 fmaf(w0v, xin[(2 * t + 0) * 32 + n], bv));
                    }
            }
        if (t > 0)
            gemm_body<4, 8>(acc, P_hh0 + w * 8192, sh_h0 + prv * 4096, sstage, lane);
        epi_lstm(acc, cst0, sh_h0 + cur * 4096, w16, lr, c2);
        __syncthreads();

        // ---------- layer 1: bias + W_ih1*h0[cur] (+ W_hh1*h1_prev) ----------
        stage_pro<4, 8>(P_ih1 + w * 8192, sstage, lane);
#pragma unroll
        for (int g = 0; g < 4; ++g)
#pragma unroll
            for (int uu = 0; uu < 2; ++uu) {
                float b = sb1[g * 128 + w16 + lr + 8 * uu];
#pragma unroll
                for (int nt = 0; nt < 4; ++nt) {
                    acc[g][nt][uu * 2 + 0] = b;
                    acc[g][nt][uu * 2 + 1] = b;
                }
            }
        gemm_body<4, 8>(acc, P_ih1 + w * 8192, sh_h0 + cur * 4096, sstage, lane);
        if (t > 0) {
            stage_pro<4, 8>(P_hh1 + w * 8192, sstage, lane);
            gemm_body<4, 8>(acc, P_hh1 + w * 8192, sh_h1 + prv * 4096, sstage, lane);
        }
        epi_lstm(acc, cst1, sh_h1 + cur * 4096, w16, lr, c2);
        __syncthreads();
    }

    const __half* hB1f = sh_h1 + ((TSTEPS - 1) & 1) * 4096;   // final h1

    // ---------- MLP layer 0: relu(b0 + W0[:,0:3]*f3 + W0[:,3:131]*h1) ----------
    {
        stage_pro<2, 8>(P_w0 + w * 4096, sstage, lane);
        float macc[2][4][4];
#pragma unroll
        for (int mt = 0; mt < 2; ++mt)
#pragma unroll
            for (int du = 0; du < 2; ++du) {
                int row = w * 32 + mt * 16 + lr + 8 * du;
                float bv = mb0[row];
                float w0v = mw0[row * 131 + 0];
                float w1v = mw0[row * 131 + 1];
                float w2v = mw0[row * 131 + 2];
#pragma unroll
                for (int nt = 0; nt < 4; ++nt)
#pragma unroll
                    for (int dd = 0; dd < 2; ++dd) {
                        int n = nt * 8 + c2 + dd;
                        float a = bv;
                        a = fmaf(w0v, f3s[0 * 32 + n], a);
                        a = fmaf(w1v, f3s[1 * 32 + n], a);
                        a = fmaf(w2v, f3s[2 * 32 + n], a);
                        macc[mt][nt][du * 2 + dd] = a;
                    }
            }
        gemm_body<2, 8>(macc, P_w0 + w * 4096, hB1f, sstage, lane);
        __syncthreads();                       // all h1 reads complete

        // relu -> m2: units 0..127 into sh_h0 buf0, 128..255 into sh_h1 buf0
#pragma unroll
        for (int mt = 0; mt < 2; ++mt)
#pragma unroll
            for (int nt = 0; nt < 4; ++nt)
#pragma unroll
                for (int idx = 0; idx < 4; ++idx) {
                    float v = fmaxf(macc[mt][nt][idx], 0.f);
                    int u = w * 32 + mt * 16 + lr + 8 * (idx >> 1);
                    int n = nt * 8 + c2 + (idx & 1);
                    if (u < 128) sh_h0[hb_widx(u, n)] = __float2half_rn(v);
                    else         sh_h1[hb_widx(u - 128, n)] = __float2half_rn(v);
                }
    }
    __syncthreads();

    // ---------- MLP layer 1: out = b1 + W1 * m2 ----------
    {
        stage_pro<2, 8>(P_w1 + w * 8192, sstage, lane);
        float oacc[2][4][4];
#pragma unroll
        for (int mt = 0; mt < 2; ++mt)
#pragma unroll
            for (int du = 0; du < 2; ++du) {
                float bv = mb1[w * 32 + mt * 16 + lr + 8 * du];
#pragma unroll
                for (int nt = 0; nt < 4; ++nt) {
                    oacc[mt][nt][du * 2 + 0] = bv;
                    oacc[mt][nt][du * 2 + 1] = bv;
                }
            }
        // K = 256: kh=0 (units 0..127) from sh_h0 buf0, kh=1 from sh_h1 buf0
        gemm_body<2, 8>(oacc, P_w1 + w * 8192, sh_h0, sstage, lane);
        stage_pro<2, 8>(P_w1 + w * 8192 + 4096, sstage, lane);
        gemm_body<2, 8>(oacc, P_w1 + w * 8192 + 4096, sh_h1, sstage, lane);

#pragma unroll
        for (int mt = 0; mt < 2; ++mt)
#pragma unroll
            for (int nt = 0; nt < 4; ++nt)
#pragma unroll
                for (int idx = 0; idx < 4; ++idx) {
                    int row = w * 32 + mt * 16 + lr + 8 * (idx >> 1);
                    int n = nt * 8 + c2 + (idx & 1);
                    out[(size_t)(track0 + n) * HID + row] = oacc[mt][nt][idx];
                }
    }
}

// ---------------- pos encoding ----------------
__global__ void pos_kernel(const float* __restrict__ tf, float* __restrict__ out)
{
    int idx = blockIdx.x * blockDim.x + threadIdx.x;
    if (idx >= NTRACK * 128) return;
    int gt = idx >> 7;
    int fi = idx & 127;
    int b = gt / NTRK, t = gt - b * NTRK;
    int coord = (fi < 64) ? 3 : 4;             // eta then phi
    float x = tf[((size_t)b * NFEAT + coord) * NTRK + t];
    int f = fi & 63;
    float p = x * g_posmul[f];
    float v = (f & 1) ? __cosf(p) : __sinf(p);
    out[(size_t)OUT_POS + (size_t)gt * 128 + fi] = v;
}

// ---------------- logpt / eta / phi passthrough ----------------
__global__ void scal_kernel(const float* __restrict__ tf, float* __restrict__ out)
{
    int gt = blockIdx.x * blockDim.x + threadIdx.x;
    if (gt >= NTRACK) return;
    int b = gt / NTRK, t = gt - b * NTRK;
    out[OUT_LOGPT + gt] = tf[((size_t)b * NFEAT + 2) * NTRK + t];
    out[OUT_ETA   + gt] = tf[((size_t)b * NFEAT + 3) * NTRK + t];
    out[OUT_PHI   + gt] = tf[((size_t)b * NFEAT + 4) * NTRK + t];
}

// ---------------- launch ----------------
extern "C" void kernel_launch(void* const* d_in, const int* in_sizes, int n_in,
                              void* d_out, int out_size)
{
    (void)in_sizes; (void)n_in; (void)out_size;
    const float* tf = (const float*)d_in[0];
    float* out = (float*)d_out;

    cudaFuncSetAttribute(lstm_mlp_kernel,
                         cudaFuncAttributeMaxDynamicSharedMemorySize, SMEM_BYTES);

    prep_kernel<<<128, 256>>>(
        (const float*)d_in[2],                       // W_hh0
        (const float*)d_in[3], (const float*)d_in[4],// b_ih0, b_hh0
        (const float*)d_in[5], (const float*)d_in[6],// W_ih1, W_hh1
        (const float*)d_in[7], (const float*)d_in[8],// b_ih1, b_hh1
        (const float*)d_in[9], (const float*)d_in[11]// mlp_w0, mlp_w1
    );

    lstm_mlp_kernel<<<NTRACK / NT_TILE, CTA_THREADS, SMEM_BYTES>>>(
        tf,
        (const float*)d_in[1],     // W_ih0
        (const float*)d_in[9],     // mlp_w0 (first 3 cols)
        (const float*)d_in[10],    // mlp_b0
        (const float*)d_in[12],    // mlp_b1
        out);

    pos_kernel<<<(NTRACK * 128 + 255) / 256, 256>>>(tf, out);
    scal_kernel<<<(NTRACK + 255) / 256, 256>>>(tf, out);
}

// round 13
// speedup vs baseline: 1.0000x; 1.0000x over previous
#include <cuda_runtime.h>
#include <cuda_fp16.h>
#include <math.h>

#define NFEAT 18
#define NTRK  1500
#define BSZ   64
#define NTRACK (BSZ*NTRK)        // 96000
#define HID   256
#define TSTEPS 6
#define NT_TILE 32               // tracks per CTA
#define CTA_THREADS 256

// output layout offsets (floats)
#define OUT_POS   24576000       // 96000*256
#define OUT_LOGPT 36864000       // + 96000*128
#define OUT_ETA   36960000
#define OUT_PHI   37056000

// dynamic smem layout (bytes)
#define H0_OFF    0              // 8192 halves (double-buffered h0)
#define H1_OFF    16384          // 8192 halves
#define SB0_OFF   32768          // 512 f32
#define SB1_OFF   34816          // 512 f32
#define WIH0_OFF  36864          // 1024 f32
#define XIN_OFF   40960          // 12*32 f32
#define F3S_OFF   42496          // 3*32 f32
#define STAGE_OFF 43008          // 8 warps * 8192 B (2 bufs x 4KB)
#define SMEM_BYTES (43008 + 8*8192)

typedef unsigned long long u64;
typedef unsigned int u32;

// ---------------- device scratch: fragment-packed fp16 weights ----------------
// LSTM mats: ((((wi*4 + g)*8 + kc)*32 + lane)*4 + reg)*2 + dd
__device__ __align__(16) __half P_hh0[65536];
__device__ __align__(16) __half P_ih1[65536];
__device__ __align__(16) __half P_hh1[65536];
__device__ __align__(16) __half P_w0 [32768];   // [8w][2mt][8kc][32][4][2]
__device__ __align__(16) __half P_w1 [65536];   // [8w][2kh][2mt][8kc][32][4][2]
__device__ __align__(16) float g_b0c[512];      // b_ih0+b_hh0, row = g*128+unit
__device__ __align__(16) float g_b1c[512];
__device__ float g_posmul[64];

// ---------------- prep: pack weights into mma fragment order ----------------
__global__ void prep_kernel(const float* __restrict__ W_hh0,
                            const float* __restrict__ b_ih0, const float* __restrict__ b_hh0,
                            const float* __restrict__ W_ih1, const float* __restrict__ W_hh1,
                            const float* __restrict__ b_ih1, const float* __restrict__ b_hh1,
                            const float* __restrict__ mw0,   const float* __restrict__ mw1)
{
    int stride = gridDim.x * blockDim.x;
    int idx0 = blockIdx.x * blockDim.x + threadIdx.x;

    for (int i = idx0; i < 65536; i += stride) {
        int dd = i & 1, reg = (i >> 1) & 3, lane = (i >> 3) & 31;
        int kc = (i >> 8) & 7, g = (i >> 11) & 3, w = (i >> 13) & 7;
        int row = g * 128 + w * 16 + (lane >> 2) + 8 * (reg & 1);
        int col = kc * 16 + (lane & 3) * 2 + dd + 8 * (reg >> 1);
        P_hh0[i] = __float2half_rn(W_hh0[row * 128 + col]);
        P_ih1[i] = __float2half_rn(W_ih1[row * 128 + col]);
        P_hh1[i] = __float2half_rn(W_hh1[row * 128 + col]);
    }
    for (int i = idx0; i < 32768; i += stride) {
        int dd = i & 1, reg = (i >> 1) & 3, lane = (i >> 3) & 31;
        int kc = (i >> 8) & 7, mt = (i >> 11) & 1, w = (i >> 12) & 7;
        int row = w * 32 + mt * 16 + (lane >> 2) + 8 * (reg & 1);
        int k   = kc * 16 + (lane & 3) * 2 + dd + 8 * (reg >> 1);
        P_w0[i] = __float2half_rn(mw0[row * 131 + 3 + k]);
    }
    // MLP1, K=256, kh-major: [8w][2kh][2mt][8kc]
    for (int i = idx0; i < 65536; i += stride) {
        int dd = i & 1, reg = (i >> 1) & 3, lane = (i >> 3) & 31;
        int kc = (i >> 8) & 7, mt = (i >> 11) & 1, kh = (i >> 12) & 1, w = (i >> 13) & 7;
        int row = w * 32 + mt * 16 + (lane >> 2) + 8 * (reg & 1);
        int k   = (kh * 8 + kc) * 16 + (lane & 3) * 2 + dd + 8 * (reg >> 1);
        P_w1[i] = __float2half_rn(mw1[row * 256 + k]);
    }
    for (int i = idx0; i < 512; i += stride) {
        g_b0c[i] = b_ih0[i] + b_hh0[i];
        g_b1c[i] = b_ih1[i] + b_hh1[i];
    }
    for (int i = idx0; i < 64; i += stride) {
        float e = (float)(2 * (i >> 1)) * (1.0f / 64.0f);
        g_posmul[i] = 6.283185307179586f / powf(10000.0f, e);
    }
}

// ---------------- activations (MUFU.TANH based) ----------------
__device__ __forceinline__ float tanh_mufu(float x) {
    float r; asm("tanh.approx.f32 %0, %1;" : "=f"(r) : "f"(x)); return r;
}
__device__ __forceinline__ float sigf(float x) {
    return fmaf(tanh_mufu(0.5f * x), 0.5f, 0.5f);
}

// ---------------- cp.async helpers ----------------
__device__ __forceinline__ void cp16(u32 dst_smem, const void* src) {
    asm volatile("cp.async.ca.shared.global [%0], [%1], 16;"
                 :: "r"(dst_smem), "l"(src));
}
__device__ __forceinline__ void cp_commit() {
    asm volatile("cp.async.commit_group;");
}
template<int N>
__device__ __forceinline__ void cp_wait() {
    asm volatile("cp.async.wait_group %0;" :: "n"(N));
}
__device__ __forceinline__ uint4 lds128(u32 addr) {
    uint4 v;
    asm volatile("ld.shared.v4.u32 {%0,%1,%2,%3}, [%4];"
                 : "=r"(v.x), "=r"(v.y), "=r"(v.z), "=r"(v.w) : "r"(addr));
    return v;
}

// ---------------- mma.sync wrapper ----------------
__device__ __forceinline__ void mma16816(float c[4], u32 a0, u32 a1, u32 a2, u32 a3,
                                         u32 b0, u32 b1) {
    asm("mma.sync.aligned.m16n8k16.row.col.f32.f16.f16.f32 "
        "{%0,%1,%2,%3}, {%4,%5,%6,%7}, {%8,%9}, {%0,%1,%2,%3};"
        : "+f"(c[0]), "+f"(c[1]), "+f"(c[2]), "+f"(c[3])
        : "r"(a0), "r"(a1), "r"(a2), "r"(a3), "r"(b0), "r"(b1));
}

// hB layout (half index): unit u = kc*16 + 2c + dd + 8kp
__device__ __forceinline__ int hb_widx(int u, int n) {
    return ((u >> 4) * 4 + ((u & 7) >> 1)) * 128 + n * 4 + ((u >> 3) & 1) * 2 + (u & 1);
}

// ---------------- staged fragment GEMM ----------------
// Stage prologue: lane-private cp.async of chunks 0,1 (2 kc each) into bufs 0,1.
template<int MT, int NKC>
__device__ __forceinline__ void stage_pro(const __half* __restrict__ pw,
                                          u32 sstage, int lane)
{
#pragma unroll
    for (int ch = 0; ch < 2; ++ch) {
#pragma unroll
        for (int kcL = 0; kcL < 2; ++kcL) {
#pragma unroll
            for (int mt = 0; mt < MT; ++mt) {
                int kc = ch * 2 + kcL;
                cp16(sstage + ch * 4096 + ((kcL * MT + mt) * 32 + lane) * 16,
                     (const void*)(pw + ((mt * NKC + kc) * 32 + lane) * 8));
            }
        }
        cp_commit();
    }
}

// Body: consume chunks from stage (LDS), refill 2 chunks ahead.
template<int MT, int NKC>
__device__ __forceinline__ void gemm_body(float acc[][4][4],
                                          const __half* __restrict__ pw,
                                          const __half* __restrict__ hB,
                                          u32 sstage, int lane)
{
    const int c = lane & 3, colr = lane >> 2;
    constexpr int NCH = NKC / 2;
#pragma unroll
    for (int ch = 0; ch < NCH; ++ch) {
        if (ch + 1 < NCH) cp_wait<1>(); else cp_wait<0>();
#pragma unroll
        for (int kcL = 0; kcL < 2; ++kcL) {
            const int kc = ch * 2 + kcL;
            u64 bv[4];
#pragma unroll
            for (int nt = 0; nt < 4; ++nt)
                bv[nt] = *reinterpret_cast<const u64*>(hB + ((kc * 4 + c) * 32 + nt * 8 + colr) * 4);
#pragma unroll
            for (int mt = 0; mt < MT; ++mt) {
                uint4 a = lds128(sstage + (ch & 1) * 4096 + ((kcL * MT + mt) * 32 + lane) * 16);
#pragma unroll
                for (int nt = 0; nt < 4; ++nt)
                    mma16816(acc[mt][nt], a.x, a.y, a.z, a.w,
                             (u32)bv[nt], (u32)(bv[nt] >> 32));
            }
        }
        if (ch + 2 < NCH) {
#pragma unroll
            for (int kcL = 0; kcL < 2; ++kcL) {
#pragma unroll
                for (int mt = 0; mt < MT; ++mt) {
                    int kc = (ch + 2) * 2 + kcL;
                    cp16(sstage + (ch & 1) * 4096 + ((kcL * MT + mt) * 32 + lane) * 16,
                         (const void*)(pw + ((mt * NKC + kc) * 32 + lane) * 8));
                }
            }
            cp_commit();
        }
    }
}

// ---------------- LSTM epilogue (16 units x 32 tracks per warp) ----------------
__device__ __forceinline__ void epi_lstm(float acc[4][4][4], float* cst, __half* hbuf,
                                         int w16, int lr, int c2)
{
#pragma unroll
    for (int nt = 0; nt < 4; ++nt)
#pragma unroll
        for (int idx = 0; idx < 4; ++idx) {
            float iv = sigf(acc[0][nt][idx]);
            float fv = sigf(acc[1][nt][idx]);
            float gv = tanh_mufu(acc[2][nt][idx]);
            float ov = sigf(acc[3][nt][idx]);
            float& cc = cst[nt * 4 + idx];
            cc = fv * cc + iv * gv;
            float h = ov * tanh_mufu(cc);
            int u = w16 + lr + 8 * (idx >> 1);
            int n = nt * 8 + c2 + (idx & 1);
            hbuf[hb_widx(u, n)] = __float2half_rn(h);
        }
}

// ---------------- fused LSTM + MLP (tensor-core, cp.async-staged weights) ----------------
__global__ void __launch_bounds__(CTA_THREADS, 2)
lstm_mlp_kernel(const float* __restrict__ tf,
                const float* __restrict__ W_ih0,   // [512][2] row-major
                const float* __restrict__ mw0,     // [256][131]
                const float* __restrict__ mb0,
                const float* __restrict__ mb1,
                float* __restrict__ out)
{
    extern __shared__ __align__(16) char smem[];
    __half* sh_h0 = (__half*)(smem + H0_OFF);      // [2][4096]
    __half* sh_h1 = (__half*)(smem + H1_OFF);      // [2][4096]
    float* sb0   = (float*)(smem + SB0_OFF);
    float* sb1   = (float*)(smem + SB1_OFF);
    float* swih0 = (float*)(smem + WIH0_OFF);
    float* xin   = (float*)(smem + XIN_OFF);       // [12][32]
    float* f3s   = (float*)(smem + F3S_OFF);       // [3][32]

    u32 smem_u32;
    { u32 a; asm("{ .reg .u64 t; cvta.to.shared.u64 t, %1; cvt.u32.u64 %0, t; }"
                 : "=r"(a) : "l"(smem)); smem_u32 = a; }

    const int tid  = threadIdx.x;
    const int lane = tid & 31;
    const int w    = tid >> 5;
    const int track0 = blockIdx.x * NT_TILE;
    const int lr = lane >> 2, c2 = (lane & 3) * 2;
    const int w16 = w * 16;
    const u32 sstage = smem_u32 + STAGE_OFF + w * 8192;

    for (int i = tid; i < 512; i += CTA_THREADS) { sb0[i] = g_b0c[i]; sb1[i] = g_b1c[i]; }
    for (int i = tid; i < 1024; i += CTA_THREADS) swih0[i] = W_ih0[i];
    for (int i = tid; i < 12 * NT_TILE; i += CTA_THREADS) {
        int f = i >> 5, n = i & 31;
        int gt = track0 + n, b = gt / NTRK, t = gt - b * NTRK;
        xin[f * 32 + n] = tf[((size_t)b * NFEAT + 6 + f) * NTRK + t];
    }
    for (int i = tid; i < 3 * NT_TILE; i += CTA_THREADS) {
        int f = i >> 5, n = i & 31;
        int gt = track0 + n, b = gt / NTRK, t = gt - b * NTRK;
        f3s[f * 32 + n] = tf[((size_t)b * NFEAT + f) * NTRK + t];
    }
    __syncthreads();

    float cst0[16], cst1[16];
#pragma unroll
    for (int i = 0; i < 16; ++i) { cst0[i] = 0.f; cst1[i] = 0.f; }

#pragma unroll 1
    for (int t = 0; t < TSTEPS; ++t) {
        const int cur = t & 1, prv = cur ^ 1;
        float acc[4][4][4];

        // ---------- layer 0: bias + W_ih0 * x_t (+ W_hh0 * h0_prev) ----------
        if (t > 0) stage_pro<4, 8>(P_hh0 + w * 8192, sstage, lane);
#pragma unroll
        for (int g = 0; g < 4; ++g)
#pragma unroll
            for (int uu = 0; uu < 2; ++uu) {
                int row = g * 128 + w16 + lr + 8 * uu;
                float bv = sb0[row];
                float w0v = swih0[row * 2 + 0];
                float w1v = swih0[row * 2 + 1];
#pragma unroll
                for (int nt = 0; nt < 4; ++nt)
#pragma unroll
                    for (int dd = 0; dd < 2; ++dd) {
                        int n = nt * 8 + c2 + dd;
                        acc[g][nt][uu * 2 + dd] =
                            fmaf(w1v, xin[(2 * t + 1) * 32 + n],
                                 fmaf(w0v, xin[(2 * t + 0) * 32 + n], bv));
                    }
            }
        if (t > 0)
            gemm_body<4, 8>(acc, P_hh0 + w * 8192, sh_h0 + prv * 4096, sstage, lane);
        epi_lstm(acc, cst0, sh_h0 + cur * 4096, w16, lr, c2);
        __syncthreads();

        // ---------- layer 1: bias + W_ih1*h0[cur] (+ W_hh1*h1_prev) ----------
        stage_pro<4, 8>(P_ih1 + w * 8192, sstage, lane);
#pragma unroll
        for (int g = 0; g < 4; ++g)
#pragma unroll
            for (int uu = 0; uu < 2; ++uu) {
                float b = sb1[g * 128 + w16 + lr + 8 * uu];
#pragma unroll
                for (int nt = 0; nt < 4; ++nt) {
                    acc[g][nt][uu * 2 + 0] = b;
                    acc[g][nt][uu * 2 + 1] = b;
                }
            }
        gemm_body<4, 8>(acc, P_ih1 + w * 8192, sh_h0 + cur * 4096, sstage, lane);
        if (t > 0) {
            stage_pro<4, 8>(P_hh1 + w * 8192, sstage, lane);
            gemm_body<4, 8>(acc, P_hh1 + w * 8192, sh_h1 + prv * 4096, sstage, lane);
        }
        epi_lstm(acc, cst1, sh_h1 + cur * 4096, w16, lr, c2);
        __syncthreads();
    }

    const __half* hB1f = sh_h1 + ((TSTEPS - 1) & 1) * 4096;   // final h1

    // ---------- MLP layer 0: relu(b0 + W0[:,0:3]*f3 + W0[:,3:131]*h1) ----------
    {
        stage_pro<2, 8>(P_w0 + w * 4096, sstage, lane);
        float macc[2][4][4];
#pragma unroll
        for (int mt = 0; mt < 2; ++mt)
#pragma unroll
            for (int du = 0; du < 2; ++du) {
                int row = w * 32 + mt * 16 + lr + 8 * du;
                float bv = mb0[row];
                float w0v = mw0[row * 131 + 0];
                float w1v = mw0[row * 131 + 1];
                float w2v = mw0[row * 131 + 2];
#pragma unroll
                for (int nt = 0; nt < 4; ++nt)
#pragma unroll
                    for (int dd = 0; dd < 2; ++dd) {
                        int n = nt * 8 + c2 + dd;
                        float a = bv;
                        a = fmaf(w0v, f3s[0 * 32 + n], a);
                        a = fmaf(w1v, f3s[1 * 32 + n], a);
                        a = fmaf(w2v, f3s[2 * 32 + n], a);
                        macc[mt][nt][du * 2 + dd] = a;
                    }
            }
        gemm_body<2, 8>(macc, P_w0 + w * 4096, hB1f, sstage, lane);
        __syncthreads();                       // all h1 reads complete

        // relu -> m2: units 0..127 into sh_h0 buf0, 128..255 into sh_h1 buf0
#pragma unroll
        for (int mt = 0; mt < 2; ++mt)
#pragma unroll
            for (int nt = 0; nt < 4; ++nt)
#pragma unroll
                for (int idx = 0; idx < 4; ++idx) {
                    float v = fmaxf(macc[mt][nt][idx], 0.f);
                    int u = w * 32 + mt * 16 + lr + 8 * (idx >> 1);
                    int n = nt * 8 + c2 + (idx & 1);
                    if (u < 128) sh_h0[hb_widx(u, n)] = __float2half_rn(v);
                    else         sh_h1[hb_widx(u - 128, n)] = __float2half_rn(v);
                }
    }
    __syncthreads();

    // ---------- MLP layer 1: out = b1 + W1 * m2 ----------
    {
        stage_pro<2, 8>(P_w1 + w * 8192, sstage, lane);
        float oacc[2][4][4];
#pragma unroll
        for (int mt = 0; mt < 2; ++mt)
#pragma unroll
            for (int du = 0; du < 2; ++du) {
                float bv = mb1[w * 32 + mt * 16 + lr + 8 * du];
#pragma unroll
                for (int nt = 0; nt < 4; ++nt) {
                    oacc[mt][nt][du * 2 + 0] = bv;
                    oacc[mt][nt][du * 2 + 1] = bv;
                }
            }
        // K = 256: kh=0 (units 0..127) from sh_h0 buf0, kh=1 from sh_h1 buf0
        gemm_body<2, 8>(oacc, P_w1 + w * 8192, sh_h0, sstage, lane);
        stage_pro<2, 8>(P_w1 + w * 8192 + 4096, sstage, lane);
        gemm_body<2, 8>(oacc, P_w1 + w * 8192 + 4096, sh_h1, sstage, lane);

#pragma unroll
        for (int mt = 0; mt < 2; ++mt)
#pragma unroll
            for (int nt = 0; nt < 4; ++nt)
#pragma unroll
                for (int idx = 0; idx < 4; ++idx) {
                    int row = w * 32 + mt * 16 + lr + 8 * (idx >> 1);
                    int n = nt * 8 + c2 + (idx & 1);
                    out[(size_t)(track0 + n) * HID + row] = oacc[mt][nt][idx];
                }
    }
}

// ---------------- pos encoding ----------------
__global__ void pos_kernel(const float* __restrict__ tf, float* __restrict__ out)
{
    int idx = blockIdx.x * blockDim.x + threadIdx.x;
    if (idx >= NTRACK * 128) return;
    int gt = idx >> 7;
    int fi = idx & 127;
    int b = gt / NTRK, t = gt - b * NTRK;
    int coord = (fi < 64) ? 3 : 4;             // eta then phi
    float x = tf[((size_t)b * NFEAT + coord) * NTRK + t];
    int f = fi & 63;
    float p = x * g_posmul[f];
    float v = (f & 1) ? __cosf(p) : __sinf(p);
    out[(size_t)OUT_POS + (size_t)gt * 128 + fi] = v;
}

// ---------------- logpt / eta / phi passthrough ----------------
__global__ void scal_kernel(const float* __restrict__ tf, float* __restrict__ out)
{
    int gt = blockIdx.x * blockDim.x + threadIdx.x;
    if (gt >= NTRACK) return;
    int b = gt / NTRK, t = gt - b * NTRK;
    out[OUT_LOGPT + gt] = tf[((size_t)b * NFEAT + 2) * NTRK + t];
    out[OUT_ETA   + gt] = tf[((size_t)b * NFEAT + 3) * NTRK + t];
    out[OUT_PHI   + gt] = tf[((size_t)b * NFEAT + 4) * NTRK + t];
}

// ---------------- launch ----------------
extern "C" void kernel_launch(void* const* d_in, const int* in_sizes, int n_in,
                              void* d_out, int out_size)
{
    (void)in_sizes; (void)n_in; (void)out_size;
    const float* tf = (const float*)d_in[0];
    float* out = (float*)d_out;

    cudaFuncSetAttribute(lstm_mlp_kernel,
                         cudaFuncAttributeMaxDynamicSharedMemorySize, SMEM_BYTES);

    prep_kernel<<<128, 256>>>(
        (const float*)d_in[2],                       // W_hh0
        (const float*)d_in[3], (const float*)d_in[4],// b_ih0, b_hh0
        (const float*)d_in[5], (const float*)d_in[6],// W_ih1, W_hh1
        (const float*)d_in[7], (const float*)d_in[8],// b_ih1, b_hh1
        (const float*)d_in[9], (const float*)d_in[11]// mlp_w0, mlp_w1
    );

    lstm_mlp_kernel<<<NTRACK / NT_TILE, CTA_THREADS, SMEM_BYTES>>>(
        tf,
        (const float*)d_in[1],     // W_ih0
        (const float*)d_in[9],     // mlp_w0 (first 3 cols)
        (const float*)d_in[10],    // mlp_b0
        (const float*)d_in[12],    // mlp_b1
        out);

    pos_kernel<<<(NTRACK * 128 + 255) / 256, 256>>>(tf, out);
    scal_kernel<<<(NTRACK + 255) / 256, 256>>>(tf, out);
}

// round 15
// speedup vs baseline: 1.3015x; 1.3015x over previous
#include <cuda_runtime.h>
#include <cuda_fp16.h>
#include <math.h>

#define NFEAT 18
#define NTRK  1500
#define BSZ   64
#define NTRACK (BSZ*NTRK)        // 96000
#define HID   256
#define TSTEPS 6
#define NT_TILE 32               // tracks per CTA
#define CTA_THREADS 256

// output layout offsets (floats)
#define OUT_POS   24576000       // 96000*256
#define OUT_LOGPT 36864000       // + 96000*128
#define OUT_ETA   36960000
#define OUT_PHI   37056000

typedef unsigned long long u64;
typedef unsigned int u32;

// ---------------- device scratch: fragment-packed fp16 weights ----------------
// LSTM mats: ((((w*4 + g)*8 + kc)*32 + lane)*4 + reg)*2 + dd
__device__ __align__(16) __half P_hh0[65536];
__device__ __align__(16) __half P_ih1[65536];
__device__ __align__(16) __half P_hh1[65536];
__device__ __align__(16) __half P_w0 [32768];   // [8w][2mt][8kc][32][4][2]
__device__ __align__(16) __half P_w1 [65536];   // [8w][2mt][16kc][32][4][2]
__device__ __align__(16) float g_b0c[512];      // b_ih0+b_hh0, row = g*128+unit
__device__ __align__(16) float g_b1c[512];
__device__ float g_posmul[64];

// ---------------- prep: pack weights into mma fragment order ----------------
__global__ void prep_kernel(const float* __restrict__ W_hh0,
                            const float* __restrict__ b_ih0, const float* __restrict__ b_hh0,
                            const float* __restrict__ W_ih1, const float* __restrict__ W_hh1,
                            const float* __restrict__ b_ih1, const float* __restrict__ b_hh1,
                            const float* __restrict__ mw0,   const float* __restrict__ mw1)
{
    int stride = gridDim.x * blockDim.x;
    int idx0 = blockIdx.x * blockDim.x + threadIdx.x;

    // LSTM hh0 / ih1 / hh1: M-tile = gate (4 per warp), K=128 (8 kc)
    for (int i = idx0; i < 65536; i += stride) {
        int dd = i & 1, reg = (i >> 1) & 3, lane = (i >> 3) & 31;
        int kc = (i >> 8) & 7, g = (i >> 11) & 3, w = (i >> 13) & 7;
        int row = g * 128 + w * 16 + (lane >> 2) + 8 * (reg & 1);
        int col = kc * 16 + (lane & 3) * 2 + dd + 8 * (reg >> 1);
        P_hh0[i] = __float2half_rn(W_hh0[row * 128 + col]);
        P_ih1[i] = __float2half_rn(W_ih1[row * 128 + col]);
        P_hh1[i] = __float2half_rn(W_hh1[row * 128 + col]);
    }
    // MLP0, K=128 part (cols 3..130 of mw0)
    for (int i = idx0; i < 32768; i += stride) {
        int dd = i & 1, reg = (i >> 1) & 3, lane = (i >> 3) & 31;
        int kc = (i >> 8) & 7, mt = (i >> 11) & 1, w = (i >> 12) & 7;
        int row = w * 32 + mt * 16 + (lane >> 2) + 8 * (reg & 1);
        int k   = kc * 16 + (lane & 3) * 2 + dd + 8 * (reg >> 1);
        P_w0[i] = __float2half_rn(mw0[row * 131 + 3 + k]);
    }
    // MLP1, K=256 (kc 0..15 spans units 0..255)
    for (int i = idx0; i < 65536; i += stride) {
        int dd = i & 1, reg = (i >> 1) & 3, lane = (i >> 3) & 31;
        int kc = (i >> 8) & 15, mt = (i >> 12) & 1, w = (i >> 13) & 7;
        int row = w * 32 + mt * 16 + (lane >> 2) + 8 * (reg & 1);
        int k   = kc * 16 + (lane & 3) * 2 + dd + 8 * (reg >> 1);
        P_w1[i] = __float2half_rn(mw1[row * 256 + k]);
    }
    for (int i = idx0; i < 512; i += stride) {
        g_b0c[i] = b_ih0[i] + b_hh0[i];
        g_b1c[i] = b_ih1[i] + b_hh1[i];
    }
    for (int i = idx0; i < 64; i += stride) {
        float e = (float)(2 * (i >> 1)) * (1.0f / 64.0f);
        g_posmul[i] = 6.283185307179586f / powf(10000.0f, e);
    }
}

// ---------------- activations (MUFU.TANH based) ----------------
__device__ __forceinline__ float tanh_mufu(float x) {
    float r; asm("tanh.approx.f32 %0, %1;" : "=f"(r) : "f"(x)); return r;
}
__device__ __forceinline__ float sigf(float x) {
    return fmaf(tanh_mufu(0.5f * x), 0.5f, 0.5f);
}
__device__ __forceinline__ u32 pack_h2(float a, float b) {
    __half2 h = __floats2half2_rn(a, b);
    return *reinterpret_cast<u32*>(&h);
}
__device__ __forceinline__ float2 unpack_h2(u32 v) {
    __half2 h = *reinterpret_cast<__half2*>(&v);
    return __half22float2(h);
}

// ---------------- mma.sync wrappers ----------------
// f32-accumulator variant (MLP)
__device__ __forceinline__ void mma16816(float c[4], u32 a0, u32 a1, u32 a2, u32 a3,
                                         u32 b0, u32 b1) {
    asm("mma.sync.aligned.m16n8k16.row.col.f32.f16.f16.f32 "
        "{%0,%1,%2,%3}, {%4,%5,%6,%7}, {%8,%9}, {%0,%1,%2,%3};"
        : "+f"(c[0]), "+f"(c[1]), "+f"(c[2]), "+f"(c[3])
        : "r"(a0), "r"(a1), "r"(a2), "r"(a3), "r"(b0), "r"(b1));
}
// f16-accumulator variant (LSTM): c[0] = halves {(lr,c2),(lr,c2+1)}, c[1] = rows +8
__device__ __forceinline__ void mma16816h(u32 c[2], u32 a0, u32 a1, u32 a2, u32 a3,
                                          u32 b0, u32 b1) {
    asm("mma.sync.aligned.m16n8k16.row.col.f16.f16.f16.f16 "
        "{%0,%1}, {%2,%3,%4,%5}, {%6,%7}, {%0,%1};"
        : "+r"(c[0]), "+r"(c[1])
        : "r"(a0), "r"(a1), "r"(a2), "r"(a3), "r"(b0), "r"(b1));
}

// hB layout (half index): unit u = kc*16 + 2c + dd + 8kp
__device__ __forceinline__ int hb_widx(int u, int n) {
    return ((u >> 4) * 4 + ((u & 7) >> 1)) * 128 + n * 4 + ((u >> 3) & 1) * 2 + (u & 1);
}

// f32-acc fragment GEMM (MLP): acc[MT][4][4] += Wpacked * B
template<int MT, int NKC>
__device__ __forceinline__ void gemm_frag(float acc[][4][4],
                                          const __half* __restrict__ pw,
                                          const __half* __restrict__ hB, int lane)
{
    const int c = lane & 3, colr = lane >> 2;
#pragma unroll
    for (int kc = 0; kc < NKC; ++kc) {
        u64 bv[4];
#pragma unroll
        for (int nt = 0; nt < 4; ++nt)
            bv[nt] = *reinterpret_cast<const u64*>(hB + ((kc * 4 + c) * 32 + nt * 8 + colr) * 4);
#pragma unroll
        for (int mt = 0; mt < MT; ++mt) {
            uint4 a = *reinterpret_cast<const uint4*>(pw + ((mt * NKC + kc) * 32 + lane) * 8);
#pragma unroll
            for (int nt = 0; nt < 4; ++nt)
                mma16816(acc[mt][nt], a.x, a.y, a.z, a.w,
                         (u32)bv[nt], (u32)(bv[nt] >> 32));
        }
    }
}

// f16-acc fragment GEMM (LSTM): acc[4][4][2] u32
template<int MT, int NKC>
__device__ __forceinline__ void gemm_frag16(u32 acc[][4][2],
                                            const __half* __restrict__ pw,
                                            const __half* __restrict__ hB, int lane)
{
    const int c = lane & 3, colr = lane >> 2;
#pragma unroll
    for (int kc = 0; kc < NKC; ++kc) {
        u64 bv[4];
#pragma unroll
        for (int nt = 0; nt < 4; ++nt)
            bv[nt] = *reinterpret_cast<const u64*>(hB + ((kc * 4 + c) * 32 + nt * 8 + colr) * 4);
#pragma unroll
        for (int mt = 0; mt < MT; ++mt) {
            uint4 a = *reinterpret_cast<const uint4*>(pw + ((mt * NKC + kc) * 32 + lane) * 8);
#pragma unroll
            for (int nt = 0; nt < 4; ++nt)
                mma16816h(acc[mt][nt], a.x, a.y, a.z, a.w,
                          (u32)bv[nt], (u32)(bv[nt] >> 32));
        }
    }
}

// ---------------- LSTM epilogue (f16 acc in, f32 math, f16 h out) ----------------
__device__ __forceinline__ void epi_lstm(u32 acc[4][4][2], float* cst, __half* hbuf,
                                         int w16, int lr, int c2)
{
#pragma unroll
    for (int nt = 0; nt < 4; ++nt)
#pragma unroll
        for (int du = 0; du < 2; ++du) {
            float2 iv2 = unpack_h2(acc[0][nt][du]);
            float2 fv2 = unpack_h2(acc[1][nt][du]);
            float2 gv2 = unpack_h2(acc[2][nt][du]);
            float2 ov2 = unpack_h2(acc[3][nt][du]);
            float iv[2] = {iv2.x, iv2.y}, fv[2] = {fv2.x, fv2.y};
            float gv[2] = {gv2.x, gv2.y}, ov[2] = {ov2.x, ov2.y};
#pragma unroll
            for (int dd = 0; dd < 2; ++dd) {
                int idx = du * 2 + dd;
                float ii = sigf(iv[dd]), ff = sigf(fv[dd]);
                float gg = tanh_mufu(gv[dd]), oo = sigf(ov[dd]);
                float& cc = cst[nt * 4 + idx];
                cc = ff * cc + ii * gg;
                float h = oo * tanh_mufu(cc);
                int u = w16 + lr + 8 * du;
                int n = nt * 8 + c2 + dd;
                hbuf[hb_widx(u, n)] = __float2half_rn(h);
            }
        }
}

// ---------------- fused LSTM + MLP (tensor-core, fp16 LSTM accumulators) ----------------
__global__ void __launch_bounds__(CTA_THREADS, 2)
lstm_mlp_kernel(const float* __restrict__ tf,
                const float* __restrict__ W_ih0,   // [512][2] row-major
                const float* __restrict__ mw0,     // [256][131]
                const float* __restrict__ mb0,
                const float* __restrict__ mb1,
                float* __restrict__ out)
{
    const int tid  = threadIdx.x;
    const int lane = tid & 31;
    const int w    = tid >> 5;
    const int track0 = blockIdx.x * NT_TILE;
    const int lr = lane >> 2, c2 = (lane & 3) * 2;
    const int w16 = w * 16;

    __shared__ __align__(16) __half sh_h0[2 * 4096];   // double-buffered h0; reused as m2B
    __shared__ __align__(16) __half sh_h1[2 * 4096];
    __shared__ float sb0[512], sb1[512], swih0[1024];
    __shared__ float xin[12][NT_TILE], f3s[3][NT_TILE];

    for (int i = tid; i < 512; i += CTA_THREADS) { sb0[i] = g_b0c[i]; sb1[i] = g_b1c[i]; }
    for (int i = tid; i < 1024; i += CTA_THREADS) swih0[i] = W_ih0[i];
    for (int i = tid; i < 12 * NT_TILE; i += CTA_THREADS) {
        int f = i >> 5, n = i & 31;
        int gt = track0 + n, b = gt / NTRK, t = gt - b * NTRK;
        xin[f][n] = tf[((size_t)b * NFEAT + 6 + f) * NTRK + t];
    }
    for (int i = tid; i < 3 * NT_TILE; i += CTA_THREADS) {
        int f = i >> 5, n = i & 31;
        int gt = track0 + n, b = gt / NTRK, t = gt - b * NTRK;
        f3s[f][n] = tf[((size_t)b * NFEAT + f) * NTRK + t];
    }
    __syncthreads();

    float cst0[16], cst1[16];
#pragma unroll
    for (int i = 0; i < 16; ++i) { cst0[i] = 0.f; cst1[i] = 0.f; }

#pragma unroll 1
    for (int t = 0; t < TSTEPS; ++t) {
        const int cur = t & 1, prv = cur ^ 1;
        u32 acc[4][4][2];

        // ---------- layer 0: acc = bias + W_ih0 * x_t (+ W_hh0 * h0_prev) ----------
#pragma unroll
        for (int g = 0; g < 4; ++g)
#pragma unroll
            for (int uu = 0; uu < 2; ++uu) {
                int row = g * 128 + w16 + lr + 8 * uu;
                float bv = sb0[row];
                float w0v = swih0[row * 2 + 0];
                float w1v = swih0[row * 2 + 1];
#pragma unroll
                for (int nt = 0; nt < 4; ++nt) {
                    float a0, a1;
                    {
                        int n = nt * 8 + c2;
                        a0 = fmaf(w1v, xin[2 * t + 1][n],
                                  fmaf(w0v, xin[2 * t + 0][n], bv));
                        a1 = fmaf(w1v, xin[2 * t + 1][n + 1],
                                  fmaf(w0v, xin[2 * t + 0][n + 1], bv));
                    }
                    acc[g][nt][uu] = pack_h2(a0, a1);
                }
            }
        if (t > 0)
            gemm_frag16<4, 8>(acc, P_hh0 + w * 8192, sh_h0 + prv * 4096, lane);
        epi_lstm(acc, cst0, sh_h0 + cur * 4096, w16, lr, c2);
        __syncthreads();

        // ---------- layer 1: acc = bias + W_ih1*h0[cur] (+ W_hh1*h1_prev) ----------
#pragma unroll
        for (int g = 0; g < 4; ++g)
#pragma unroll
            for (int uu = 0; uu < 2; ++uu) {
                u32 bp = pack_h2(sb1[g * 128 + w16 + lr + 8 * uu],
                                 sb1[g * 128 + w16 + lr + 8 * uu]);
#pragma unroll
                for (int nt = 0; nt < 4; ++nt)
                    acc[g][nt][uu] = bp;
            }
        gemm_frag16<4, 8>(acc, P_ih1 + w * 8192, sh_h0 + cur * 4096, lane);
        if (t > 0)
            gemm_frag16<4, 8>(acc, P_hh1 + w * 8192, sh_h1 + prv * 4096, lane);
        epi_lstm(acc, cst1, sh_h1 + cur * 4096, w16, lr, c2);
        __syncthreads();
    }

    const __half* hB1f = sh_h1 + ((TSTEPS - 1) & 1) * 4096;   // final h1

    // ---------- MLP layer 0 (f32 acc): relu(b0 + W0[:,0:3]*f3 + W0[:,3:131]*h1) ----------
    {
        float macc[2][4][4];
#pragma unroll
        for (int mt = 0; mt < 2; ++mt)
#pragma unroll
            for (int du = 0; du < 2; ++du) {
                int row = w * 32 + mt * 16 + lr + 8 * du;
                float bv = mb0[row];
                float w0v = mw0[row * 131 + 0];
                float w1v = mw0[row * 131 + 1];
                float w2v = mw0[row * 131 + 2];
#pragma unroll
                for (int nt = 0; nt < 4; ++nt)
#pragma unroll
                    for (int dd = 0; dd < 2; ++dd) {
                        int n = nt * 8 + c2 + dd;
                        float a = bv;
                        a = fmaf(w0v, f3s[0][n], a);
                        a = fmaf(w1v, f3s[1][n], a);
                        a = fmaf(w2v, f3s[2][n], a);
                        macc[mt][nt][du * 2 + dd] = a;
                    }
            }
        gemm_frag<2, 8>(macc, P_w0 + w * 4096, hB1f, lane);

        // relu -> m2B (overlays sh_h0, 256 units -> 8192 halves)
        __half* m2B = sh_h0;
#pragma unroll
        for (int mt = 0; mt < 2; ++mt)
#pragma unroll
            for (int nt = 0; nt < 4; ++nt)
#pragma unroll
                for (int idx = 0; idx < 4; ++idx) {
                    float v = fmaxf(macc[mt][nt][idx], 0.f);
                    int u = w * 32 + mt * 16 + lr + 8 * (idx >> 1);
                    int n = nt * 8 + c2 + (idx & 1);
                    m2B[hb_widx(u, n)] = __float2half_rn(v);
                }
    }
    __syncthreads();

    // ---------- MLP layer 1 (f32 acc): out = b1 + W1 * m2 ----------
    {
        float oacc[2][4][4];
#pragma unroll
        for (int mt = 0; mt < 2; ++mt)
#pragma unroll
            for (int du = 0; du < 2; ++du) {
                float bv = mb1[w * 32 + mt * 16 + lr + 8 * du];
#pragma unroll
                for (int nt = 0; nt < 4; ++nt) {
                    oacc[mt][nt][du * 2 + 0] = bv;
                    oacc[mt][nt][du * 2 + 1] = bv;
                }
            }
        gemm_frag<2, 16>(oacc, P_w1 + w * 8192, sh_h0, lane);

#pragma unroll
        for (int mt = 0; mt < 2; ++mt)
#pragma unroll
            for (int nt = 0; nt < 4; ++nt)
#pragma unroll
                for (int idx = 0; idx < 4; ++idx) {
                    int row = w * 32 + mt * 16 + lr + 8 * (idx >> 1);
                    int n = nt * 8 + c2 + (idx & 1);
                    out[(size_t)(track0 + n) * HID + row] = oacc[mt][nt][idx];
                }
    }
}

// ---------------- pos encoding ----------------
__global__ void pos_kernel(const float* __restrict__ tf, float* __restrict__ out)
{
    int idx = blockIdx.x * blockDim.x + threadIdx.x;
    if (idx >= NTRACK * 128) return;
    int gt = idx >> 7;
    int fi = idx & 127;
    int b = gt / NTRK, t = gt - b * NTRK;
    int coord = (fi < 64) ? 3 : 4;             // eta then phi
    float x = tf[((size_t)b * NFEAT + coord) * NTRK + t];
    int f = fi & 63;
    float p = x * g_posmul[f];
    float v = (f & 1) ? __cosf(p) : __sinf(p);
    out[(size_t)OUT_POS + (size_t)gt * 128 + fi] = v;
}

// ---------------- logpt / eta / phi passthrough ----------------
__global__ void scal_kernel(const float* __restrict__ tf, float* __restrict__ out)
{
    int gt = blockIdx.x * blockDim.x + threadIdx.x;
    if (gt >= NTRACK) return;
    int b = gt / NTRK, t = gt - b * NTRK;
    out[OUT_LOGPT + gt] = tf[((size_t)b * NFEAT + 2) * NTRK + t];
    out[OUT_ETA   + gt] = tf[((size_t)b * NFEAT + 3) * NTRK + t];
    out[OUT_PHI   + gt] = tf[((size_t)b * NFEAT + 4) * NTRK + t];
}

// ---------------- launch ----------------
extern "C" void kernel_launch(void* const* d_in, const int* in_sizes, int n_in,
                              void* d_out, int out_size)
{
    (void)in_sizes; (void)n_in; (void)out_size;
    const float* tf = (const float*)d_in[0];
    float* out = (float*)d_out;

    prep_kernel<<<128, 256>>>(
        (const float*)d_in[2],                       // W_hh0
        (const float*)d_in[3], (const float*)d_in[4],// b_ih0, b_hh0
        (const float*)d_in[5], (const float*)d_in[6],// W_ih1, W_hh1
        (const float*)d_in[7], (const float*)d_in[8],// b_ih1, b_hh1
        (const float*)d_in[9], (const float*)d_in[11]// mlp_w0, mlp_w1
    );

    lstm_mlp_kernel<<<NTRACK / NT_TILE, CTA_THREADS>>>(
        tf,
        (const float*)d_in[1],     // W_ih0
        (const float*)d_in[9],     // mlp_w0 (first 3 cols)
        (const float*)d_in[10],    // mlp_b0
        (const float*)d_in[12],    // mlp_b1
        out);

    pos_kernel<<<(NTRACK * 128 + 255) / 256, 256>>>(tf, out);
    scal_kernel<<<(NTRACK + 255) / 256, 256>>>(tf, out);
}